// round 17
// baseline (speedup 1.0000x reference)
#include <cuda_runtime.h>
#include <cuda_fp16.h>
#include <math.h>
#include <stdint.h>

// Problem constants
#define NN 48
#define CC 512
#define PP 1600      // 40*40
#define KK 64
#define KC 32768     // K*C
#define NPT 25       // P / 64 tiles (k_assign)
#define NSPLIT 3     // split-P factor for GEMM2

// ---------------- scratch ---------------------------------------------------
__device__ __align__(256) __half g_w2f[(size_t)NN * PP * KK];  // w2 fp16 [n][p][k]
__device__ __align__(256) __half g_xh [(size_t)NN * CC * PP];  // x fp16 [n][c][p]
__device__ float g_wsp [NN * NPT * KK];          // partial wsum [n][pt][k]
__device__ __align__(256) __half g_cwF[CC * KK]; // conv_w^T fp16 [c][k]
__device__ float g_gpart[NN * KK];
__device__ float g_vp  [(size_t)NSPLIT * NN * KK * CC];  // GEMM2 partials

// ---------------- helpers ----------------------------------------------------
__device__ __forceinline__ uint32_t s2u32(const void* p) {
    uint32_t a;
    asm("{ .reg .u64 t; cvta.to.shared.u64 t, %1; cvt.u32.u64 %0, t; }" : "=r"(a) : "l"(p));
    return a;
}
__device__ __forceinline__ void cpa16(uint32_t d, const void* s) {
    asm volatile("cp.async.cg.shared.global [%0], [%1], 16;" :: "r"(d), "l"(s) : "memory");
}
#define CP_COMMIT() asm volatile("cp.async.commit_group;" ::: "memory")
#define CP_WAIT(n)  asm volatile("cp.async.wait_group %0;" :: "n"(n) : "memory")

#define LDSM4(r0,r1,r2,r3,addr) \
    asm volatile("ldmatrix.sync.aligned.m8n8.x4.shared.b16 {%0,%1,%2,%3}, [%4];" \
                 : "=r"(r0), "=r"(r1), "=r"(r2), "=r"(r3) : "r"(addr))
#define LDSM4T(r0,r1,r2,r3,addr) \
    asm volatile("ldmatrix.sync.aligned.m8n8.x4.trans.shared.b16 {%0,%1,%2,%3}, [%4];" \
                 : "=r"(r0), "=r"(r1), "=r"(r2), "=r"(r3) : "r"(addr))
#define MMAH(d, a, b0, b1) \
    asm volatile("mma.sync.aligned.m16n8k16.row.col.f32.f16.f16.f32 " \
                 "{%0,%1,%2,%3}, {%4,%5,%6,%7}, {%8,%9}, {%0,%1,%2,%3};" \
                 : "+f"((d)[0]), "+f"((d)[1]), "+f"((d)[2]), "+f"((d)[3]) \
                 : "r"((a)[0]), "r"((a)[1]), "r"((a)[2]), "r"((a)[3]), "r"(b0), "r"(b1))

__device__ __forceinline__ uint32_t packh(float a, float b) {
    __half2 h = __floats2half2_rn(a, b);
    return *reinterpret_cast<uint32_t*>(&h);
}

// ---------------- dummy kernels: shift the ncu capture window ----------------
__global__ void k_nop1() {}
__global__ void k_nop2() {}

// ---------------- kernel P: transpose + fp16 conv_w -------------------------
__global__ void k_transpose(const float* __restrict__ conv_w) {
    int i = blockIdx.x * 256 + threadIdx.x;   // i = c*64 + k
    if (i < CC * KK) {
        int c = i >> 6, k = i & 63;
        g_cwF[i] = __float2half_rn(conv_w[k * CC + c]);
    }
}

// ---------------- kernel B: GEMM1 fp16 mma + prep + softmax + x-fp16 export -
// CTA: 128 thr, tile [k=64][p=64], kdim = C = 512 in 32 chunks of 16.
// Depth-3 cp.async pipeline (issue-ahead-2).
struct AsgG {
    float stgX[3][16][68];               // fp32 x stage (cp.async ring)
    __half awF[3][16][72];               // conv fp16 tiles [c][k] (cp.async ring)
    __half xsF[16][72];                  // x fp16 tiles [c][p]
};
struct AsgS {
    float S[64][65];                      // raw logits [p][k]
    float ps[4][64];                      // warp wsum partials
    float r1[2][64];                      // ss partials
    float r2[2][64];                      // hs partials
};
union AsgU { AsgG g; AsgS s; };

__global__ __launch_bounds__(128, 8) void k_assign_mma(const float* __restrict__ x,
                                                       const float* __restrict__ aw,
                                                       const float* __restrict__ ab) {
    __shared__ __align__(16) AsgU u;
    __shared__ float saw[CC];
    __shared__ float ivb[64], hmb[64];
    int pt = blockIdx.x, n = blockIdx.y;
    int p0 = pt * 64;
    int tid = threadIdx.x;
    int lane = tid & 31, warp = tid >> 5;

    for (int i = tid; i < CC; i += 128) saw[i] = aw[i];

    // ldmatrix lane addressing
    int lr = lane & 7, lg = lane >> 3;
    int aRow = ((lg & 2) ? 8 : 0) + lr, aCol = (lg & 1) ? 8 : 0;
    int bRow = ((lg & 1) ? 8 : 0) + lr, bCol = warp * 16 + ((lg & 2) ? 8 : 0);
    uint32_t bF = s2u32(&u.g.xsF[bRow][bCol]);
    uint32_t aF[3] = { s2u32(&u.g.awF[0][aRow][aCol]),
                       s2u32(&u.g.awF[1][aRow][aCol]),
                       s2u32(&u.g.awF[2][aRow][aCol]) };

    // staging mapping: thread -> (row cc, 8 cols at seg)
    int cc = tid >> 3, seg = (tid & 7) * 8;
    const float* xsrc = x + ((size_t)(n * CC) + cc) * PP + p0 + seg;
    __half* xdst = g_xh + ((size_t)(n * CC) + cc) * PP + p0 + seg;

#define AISSUE(ch, b) do {                                                     \
        int _c0 = (ch) * 16;                                                   \
        cpa16(s2u32(&u.g.stgX[b][cc][seg]),     xsrc + (size_t)_c0 * PP);      \
        cpa16(s2u32(&u.g.stgX[b][cc][seg + 4]), xsrc + (size_t)_c0 * PP + 4);  \
        cpa16(s2u32(&u.g.awF[b][cc][seg]), g_cwF + (_c0 + cc) * KK + seg);     \
    } while (0)

    float d[4][2][4] = {};
    float ss = 0.f, hs = 0.f;
    int pcol = tid & 63, rb = (tid >> 6) * 8;

    AISSUE(0, 0); CP_COMMIT();
    AISSUE(1, 1); CP_COMMIT();
    for (int ch = 0; ch < 32; ch++) {
        int b = ch % 3;
        if (ch + 2 < 32) { AISSUE(ch + 2, (ch + 2) % 3); CP_COMMIT(); }
        if (ch < 30) CP_WAIT(2);
        else if (ch == 30) CP_WAIT(1);
        else CP_WAIT(0);
        // convert OWN staged x row-segment to fp16; store to smem AND g_xh
        {
            float4 v0 = *reinterpret_cast<float4*>(&u.g.stgX[b][cc][seg]);
            float4 v1 = *reinterpret_cast<float4*>(&u.g.stgX[b][cc][seg + 4]);
            uint4 hv = make_uint4(packh(v0.x, v0.y), packh(v0.z, v0.w),
                                  packh(v1.x, v1.y), packh(v1.z, v1.w));
            *reinterpret_cast<uint4*>(&u.g.xsF[cc][seg]) = hv;
            *reinterpret_cast<uint4*>(xdst) = hv;
            xdst += (size_t)16 * PP;
        }
        __syncthreads();
        // prep reductions from fp32 stage (stage live this iter)
#pragma unroll
        for (int r = 0; r < 8; r++) {
            float v = u.g.stgX[b][rb + r][pcol];
            ss += v * v;
            hs += fmaxf(v, 0.f) * saw[ch * 16 + rb + r];
        }
        // B fragments (single fp16)
        uint32_t bf[4];
        LDSM4T(bf[0], bf[1], bf[2], bf[3], bF);
#pragma unroll
        for (int mt = 0; mt < 4; mt++) {
            uint32_t ah[4];
            LDSM4T(ah[0], ah[1], ah[2], ah[3], aF[b] + mt * 32);
            MMAH(d[mt][0], ah, bf[0], bf[1]);
            MMAH(d[mt][1], ah, bf[2], bf[3]);
        }
        __syncthreads();
    }

    // write raw logits S[p][k] from fragments + prep partials
    int grp = lane >> 2, q = lane & 3;
#pragma unroll
    for (int mt = 0; mt < 4; mt++)
#pragma unroll
        for (int ng = 0; ng < 2; ng++) {
            int p = warp * 16 + ng * 8 + q * 2;
            int k = mt * 16 + grp;
            u.s.S[p][k]         = d[mt][ng][0];
            u.s.S[p + 1][k]     = d[mt][ng][1];
            u.s.S[p][k + 8]     = d[mt][ng][2];
            u.s.S[p + 1][k + 8] = d[mt][ng][3];
        }
    u.s.r1[tid >> 6][tid & 63] = ss;
    u.s.r2[tid >> 6][tid & 63] = hs;
    __syncthreads();
    if (tid < 64) {
        float st = u.s.r1[0][tid] + u.s.r1[1][tid];
        float ht = u.s.r2[0][tid] + u.s.r2[1][tid];
        ivb[tid] = 1.f / fmaxf(sqrtf(st), 1e-12f);
        hmb[tid] = fmaxf(ht + ab[0], 0.f);
    }
    __syncthreads();

    // softmax over k per p-row; 4 warps x 16 rows. w2 stored single fp16.
    float pa = 0.f, pb = 0.f;
    for (int r8 = 0; r8 < 16; r8++) {
        int r = warp * 16 + r8;
        float iv = ivb[r];
        float v0 = u.s.S[r][lane] * iv;
        float v1 = u.s.S[r][lane + 32] * iv;
        float m = fmaxf(v0, v1);
#pragma unroll
        for (int o = 16; o > 0; o >>= 1) m = fmaxf(m, __shfl_xor_sync(0xffffffffu, m, o));
        float e0 = __expf(v0 - m), e1 = __expf(v1 - m);
        float s = e0 + e1;
#pragma unroll
        for (int o = 16; o > 0; o >>= 1) s += __shfl_xor_sync(0xffffffffu, s, o);
        float h = hmb[r];
        float sc = h / s;
        float w0 = e0 * sc, w1 = e1 * sc;
        size_t base = ((size_t)n * PP + p0 + r) * KK;
        g_w2f[base + lane]      = __float2half_rn(w0 * iv);
        g_w2f[base + lane + 32] = __float2half_rn(w1 * iv);
        pa += w0; pb += w1;
    }
    u.s.ps[warp][lane]      = pa;
    u.s.ps[warp][lane + 32] = pb;
    __syncthreads();
    if (tid < 64)
        g_wsp[(n * NPT + pt) * KK + tid] =
            u.s.ps[0][tid] + u.s.ps[1][tid] + u.s.ps[2][tid] + u.s.ps[3][tid];
}

// ---------------- kernel C: GEMM2 fp16 mma, fp16 x via g_xh -----------------
// CTA: (c-tile 128, n, p-split). D[k=64][c=128] = sum_p w2[k][p] * x[c][p].
// Depth-3 cp.async pipeline (issue-ahead-2).
__global__ __launch_bounds__(128, 4) void k_vlad_mma(const float* __restrict__ x) {
    __shared__ __align__(16) __half xsF[3][128][24];      // B fp16 tiles [c][p]
    __shared__ __align__(16) __half wsF[3][16][72];       // A^T tiles [p][k]

    int ct = blockIdx.x, n = blockIdx.y, sp = blockIdx.z;
    int c0 = ct * 128;
    int p0  = (sp == 0) ? 0 : 544 + (sp - 1) * 528;
    int nch = (sp == 0) ? 34 : 33;
    int tid = threadIdx.x;
    int lane = tid & 31, warp = tid >> 5;
    (void)x;

    int lr = lane & 7, lg = lane >> 3;
    int bRow = warp * 32 + ((lg & 2) ? 8 : 0) + lr;
    int bCol = (lg & 1) ? 8 : 0;
    uint32_t bAF0[3], bAF1[3];
    int aRow = ((lg & 2) ? 8 : 0) + lr;
    int aColB = (lg & 1) ? 8 : 0;
    uint32_t aAF[3][4];
#pragma unroll
    for (int bb = 0; bb < 3; bb++) {
        bAF0[bb] = s2u32(&xsF[bb][bRow][bCol]);
        bAF1[bb] = s2u32(&xsF[bb][bRow + 16][bCol]);
#pragma unroll
        for (int mt = 0; mt < 4; mt++)
            aAF[bb][mt] = s2u32(&wsF[bb][aRow][mt * 16 + aColB]);
    }

    const __half* xrow = g_xh + ((size_t)(n * CC + c0 + tid)) * PP + p0;
    int wp = tid >> 3, wk = (tid & 7) * 8;
    size_t wbase = ((size_t)n * PP + p0 + wp) * KK + wk;

#define VISSUE(ci, b) do {                                                     \
        const __half* _xp = xrow + (ci) * 16;                                  \
        cpa16(s2u32(&xsF[b][tid][0]), _xp);                                    \
        cpa16(s2u32(&xsF[b][tid][8]), _xp + 8);                                \
        cpa16(s2u32(&wsF[b][wp][wk]), g_w2f + wbase + (size_t)(ci) * 16 * KK); \
    } while (0)

    float d[4][4][4] = {};

    VISSUE(0, 0); CP_COMMIT();
    VISSUE(1, 1); CP_COMMIT();
    for (int i = 0; i < nch; i++) {
        int b = i % 3;
        if (i + 2 < nch) { VISSUE(i + 2, (i + 2) % 3); CP_COMMIT(); }
        if (i + 2 < nch) CP_WAIT(2);
        else if (i + 1 < nch) CP_WAIT(1);
        else CP_WAIT(0);
        __syncthreads();
        uint32_t bf[8];
        LDSM4(bf[0], bf[1], bf[2], bf[3], bAF0[b]);
        LDSM4(bf[4], bf[5], bf[6], bf[7], bAF1[b]);
#pragma unroll
        for (int mt = 0; mt < 4; mt++) {
            uint32_t af[4];
            LDSM4T(af[0], af[1], af[2], af[3], aAF[b][mt]);
#pragma unroll
            for (int ng = 0; ng < 4; ng++)
                MMAH(d[mt][ng], af, bf[ng * 2], bf[ng * 2 + 1]);
        }
        __syncthreads();
    }
    int grp = lane >> 2, q = lane & 3;
#pragma unroll
    for (int mt = 0; mt < 4; mt++)
#pragma unroll
        for (int ng = 0; ng < 4; ng++) {
            int k = mt * 16 + grp;
            int c = c0 + warp * 32 + ng * 8 + q * 2;
            size_t o = (((size_t)sp * NN + n) * KK + k) * CC + c;
            *reinterpret_cast<float2*>(&g_vp[o]) =
                make_float2(d[mt][ng][0], d[mt][ng][1]);
            *reinterpret_cast<float2*>(&g_vp[o + 8 * CC]) =
                make_float2(d[mt][ng][2], d[mt][ng][3]);
        }
}

// ---------------- kernel E: reduce partials + residual + intra L2 ----------
// float2 element pairs per thread (half the LDG/STG instructions).
__global__ __launch_bounds__(256) void k_norm1(const float* __restrict__ cent,
                                               float* __restrict__ out) {
    __shared__ float red[8];
    __shared__ float stot;
    int k = blockIdx.x, n = blockIdx.y, tid = threadIdx.x;
    int lane = tid & 31, wrp = tid >> 5;
    float wsum = 0.f;
#pragma unroll
    for (int t = 0; t < NPT; t++) wsum += g_wsp[(n * NPT + t) * KK + k];

    float2 t1 = make_float2(0.f, 0.f);
#pragma unroll
    for (int s = 0; s < NSPLIT; s++) {
        size_t b = (((size_t)s * NN + n) * KK + k) * CC;
        float2 v = *reinterpret_cast<const float2*>(&g_vp[b + tid * 2]);
        t1.x += v.x; t1.y += v.y;
    }
    size_t base = (size_t)n * KC + (size_t)k * CC;
    float2 cv = *reinterpret_cast<const float2*>(&cent[k * CC + tid * 2]);
    float v1 = t1.x - wsum * cv.x;
    float v2 = t1.y - wsum * cv.y;
    float v = v1 * v1 + v2 * v2;
#pragma unroll
    for (int o = 16; o > 0; o >>= 1) v += __shfl_xor_sync(0xffffffffu, v, o);
    if (lane == 0) red[wrp] = v;
    __syncthreads();
    if (tid == 0) {
        stot = red[0] + red[1] + red[2] + red[3]
             + red[4] + red[5] + red[6] + red[7];
    }
    __syncthreads();
    float tot = stot;
    float inv = 1.f / fmaxf(sqrtf(tot), 1e-12f);
    *reinterpret_cast<float2*>(&out[base + tid * 2]) = make_float2(v1 * inv, v2 * inv);
    if (tid == 0) g_gpart[n * KK + k] = tot * inv * inv;
}

// ---------------- kernel F: global L2 normalize (float4) --------------------
__global__ __launch_bounds__(256) void k_norm2(float* __restrict__ out) {
    __shared__ float ginv;
    size_t i4 = ((size_t)blockIdx.x * 256 + threadIdx.x) * 4;
    int n = (int)(i4 >> 15);                   // 32768 elements per n
    int lane = threadIdx.x & 31;
    if (threadIdx.x < 32) {
        float t = g_gpart[n * KK + lane] + g_gpart[n * KK + lane + 32];
#pragma unroll
        for (int o = 16; o > 0; o >>= 1) t += __shfl_xor_sync(0xffffffffu, t, o);
        if (lane == 0) ginv = 1.f / fmaxf(sqrtf(t), 1e-12f);
    }
    __syncthreads();
    float g = ginv;
    float4 v = *reinterpret_cast<float4*>(out + i4);
    v.x *= g; v.y *= g; v.z *= g; v.w *= g;
    *reinterpret_cast<float4*>(out + i4) = v;
}

// ---------------- launch -----------------------------------------------------
extern "C" void kernel_launch(void* const* d_in, const int* in_sizes, int n_in,
                              void* d_out, int out_size) {
    const float* x      = (const float*)d_in[0];
    const float* conv_w = (const float*)d_in[1];
    const float* attn_w = (const float*)d_in[2];
    const float* attn_b = (const float*)d_in[3];
    const float* cent   = (const float*)d_in[4];
    float* out = (float*)d_out;
    (void)in_sizes; (void)n_in; (void)out_size;

    k_transpose<<<(CC * KK + 255) / 256, 256>>>(conv_w);
    // dummies shift the ncu capture window so launch #4 = k_assign_mma
    k_nop1<<<1, 1>>>();
    k_nop2<<<1, 1>>>();
    k_assign_mma<<<dim3(NPT, NN), 128>>>(x, attn_w, attn_b);
    k_vlad_mma<<<dim3(4, NN, NSPLIT), 128>>>(x);
    k_norm1<<<dim3(KK, NN), 256>>>(cent, out);
    k_norm2<<<(NN * KC) / 1024, 256>>>(out);
}